// round 16
// baseline (speedup 1.0000x reference)
#include <cuda_runtime.h>
#include <cstdint>

#define B_    128
#define S_    1024
#define EMB_  100
#define EDIM_ 256
#define H_    1024

// Scratch (device globals: allocation-free rule)
__device__ float       g_I[S_ * B_ * H_];      // [s*128+b][h]  512 MB
__device__ signed char g_Xq[S_ * B_ * EDIM_];  // quantized layer-1 acts *16
__device__ signed char g_W2q[H_ * EDIM_];      // round(W2*16)
__device__ signed char g_Wrq[H_ * H_];         // round(Wr2*16)
__device__ float       g_sum[B_ * H_];         // spike counts

__device__ __forceinline__ uint32_t smem_u32(const void* p) {
    uint32_t a;
    asm("{ .reg .u64 t; cvta.to.shared.u64 t, %1; cvt.u32.u64 %0, t; }" : "=r"(a) : "l"(p));
    return a;
}

// ---------------- K0: weight quantization --------------------------------
__global__ void k_quant(const float* __restrict__ W2, const float* __restrict__ Wr2) {
    int i = blockIdx.x * blockDim.x + threadIdx.x;
    if (i < H_ * EDIM_) {
        float v = rintf(W2[i] * 16.f);
        v = fminf(fmaxf(v, -15.f), 15.f);
        g_W2q[i] = (signed char)v;
    }
    if (i < H_ * H_) {
        float v = rintf(Wr2[i] * 16.f);
        v = fminf(fmaxf(v, -15.f), 15.f);
        g_Wrq[i] = (signed char)v;
    }
}

// ---------------- K1: embedding + layer1 + quant_act ----------------------
__global__ __launch_bounds__(256) void k_embed_l1(
    const int* __restrict__ inputs, const float* __restrict__ emb,
    const float* __restrict__ W1, const float* __restrict__ b1)
{
    extern __shared__ char sm[];
    float* w1t = (float*)sm;               // [100][257]
    float* xs  = (float*)(sm + 102912);    // [64][104]
    float* b1s = (float*)(sm + 129536);
    int*   tok = (int*)(sm + 130560);

    int t = threadIdx.x;
    for (int idx = t; idx < EDIM_ * EMB_; idx += 256) {
        int h = idx / EMB_;
        int e = idx - h * EMB_;
        w1t[e * 257 + h] = W1[idx];
    }
    b1s[t] = b1[t];
    int r0 = blockIdx.x * 64;
    if (t < 64) {
        int R = r0 + t;
        tok[t] = inputs[(R & 127) * S_ + (R >> 7)];
    }
    __syncthreads();
    for (int idx = t; idx < 64 * 104; idx += 256) {
        int r = idx / 104;
        int e = idx - r * 104;
        xs[idx] = (e < EMB_) ? emb[tok[r] * EMB_ + e] : 0.f;
    }
    __syncthreads();

    int h = t;
    for (int rb = 0; rb < 8; rb++) {
        float acc[8];
#pragma unroll
        for (int i = 0; i < 8; i++) acc[i] = 0.f;
        for (int ec = 0; ec < 25; ec++) {
            float w0 = w1t[(4 * ec + 0) * 257 + h];
            float w1v = w1t[(4 * ec + 1) * 257 + h];
            float w2v = w1t[(4 * ec + 2) * 257 + h];
            float w3v = w1t[(4 * ec + 3) * 257 + h];
#pragma unroll
            for (int r8 = 0; r8 < 8; r8++) {
                const float4 x4 = *(const float4*)(xs + (rb * 8 + r8) * 104 + 4 * ec);
                acc[r8] += x4.x * w0 + x4.y * w1v + x4.z * w2v + x4.w * w3v;
            }
        }
#pragma unroll
        for (int r8 = 0; r8 < 8; r8++) {
            int R = r0 + rb * 8 + r8;
            float v = acc[r8] + b1s[h];
            v = fmaxf(v, 0.f);
            float q = fminf(rintf(v * 16.f), 15.f);
            g_Xq[R * EDIM_ + h] = (signed char)q;
        }
    }
}

// ---------------- K2: I = Xq @ W2q^T / 256 (IMMA + coalesced epilogue) ------
__global__ __launch_bounds__(256, 2) void k_gemm_I() {
    extern __shared__ char sm[];
    // [0, 32768)        W2 tile: 128 rows x 256 B, 16B-unit XOR swizzle
    // [32768, 67584)    Xq tile: 128 rows x 272 B
    // [67584, 71808)    stage: 8 rows x 132 floats
    int t = threadIdx.x, lane = t & 31, w = t >> 5;
    int ht0 = blockIdx.x * 128;
    int rt0 = blockIdx.y * 128;
    uint32_t smb = smem_u32(sm);
    float* stage = (float*)(sm + 67584);

    const int4* W24 = (const int4*)g_W2q;
    int4* wS2 = (int4*)sm;
    for (int idx = t; idx < 2048; idx += 256) {
        int hh = idx >> 4, u = idx & 15;
        wS2[hh * 16 + (u ^ (hh & 7))] = W24[(ht0 + hh) * 16 + u];
    }
    {
        const unsigned long long* Xs =
            (const unsigned long long*)(g_Xq + (size_t)rt0 * 256);
#pragma unroll
        for (int j = 0; j < 16; j++) {
            int idx = t + j * 256;
            int row = idx >> 5, u = idx & 31;
            *(unsigned long long*)(sm + 32768 + row * 272 + u * 8) = Xs[row * 32 + u];
        }
    }
    __syncthreads();

    int mm = lane >> 3, r8 = lane & 7;
    int lrow = 16 * w + ((mm & 1) << 3) + r8;
    int uhi = mm >> 1;
    uint32_t arow = smb + (uint32_t)lrow * 256u;
    unsigned aR[8][4];
#pragma unroll
    for (int kc = 0; kc < 8; kc++) {
        uint32_t aaddr = arow + (uint32_t)(((kc * 2 + uhi) ^ r8) << 4);
        asm volatile(
            "ldmatrix.sync.aligned.m8n8.x4.shared.b16 {%0,%1,%2,%3}, [%4];"
            : "=r"(aR[kc][0]), "=r"(aR[kc][1]), "=r"(aR[kc][2]), "=r"(aR[kc][3])
            : "r"(aaddr));
    }

    int qd = lane >> 2, qm = lane & 3;
    int cw = 16 * w + qd;               // local output column
    uint32_t xb0 = smb + 32768u + (uint32_t)(qd * 272 + qm * 4);

    for (int n = 0; n < 16; n++) {
        uint32_t xb = xb0 + (uint32_t)(n * 8 * 272);
        int c[8];
#pragma unroll
        for (int i = 0; i < 8; i++) c[i] = 0;
#pragma unroll
        for (int kc = 0; kc < 8; kc++) {
            unsigned b0v, b1v;
            asm volatile("ld.shared.b32 %0, [%1];" : "=r"(b0v) : "r"(xb + kc * 32));
            asm volatile("ld.shared.b32 %0, [%1];" : "=r"(b1v) : "r"(xb + kc * 32 + 16));
            int* cc = c + (kc & 1) * 4;
            asm volatile(
                "mma.sync.aligned.m16n8k32.row.col.s32.s8.s8.s32 "
                "{%0,%1,%2,%3}, {%4,%5,%6,%7}, {%8,%9}, {%0,%1,%2,%3};"
                : "+r"(cc[0]), "+r"(cc[1]), "+r"(cc[2]), "+r"(cc[3])
                : "r"(aR[kc][0]), "r"(aR[kc][1]), "r"(aR[kc][2]), "r"(aR[kc][3]),
                  "r"(b0v), "r"(b1v));
        }
        stage[(qm * 2    ) * 132 + cw    ] = (float)(c[0] + c[4]) * (1.f / 256.f);
        stage[(qm * 2 + 1) * 132 + cw    ] = (float)(c[1] + c[5]) * (1.f / 256.f);
        stage[(qm * 2    ) * 132 + cw + 8] = (float)(c[2] + c[6]) * (1.f / 256.f);
        stage[(qm * 2 + 1) * 132 + cw + 8] = (float)(c[3] + c[7]) * (1.f / 256.f);
        __syncthreads();
        {
            float4 v = *(float4*)(stage + w * 132 + lane * 4);
            *(float4*)(&g_I[(size_t)(rt0 + n * 8 + w) * 1024 + ht0 + lane * 4]) = v;
        }
        __syncthreads();
    }
}

// ---------------- K3: recurrent LIF scan (v15: fused dual-group CTA) --------
// 8 clusters x 16 CTAs x 512 threads. One CTA = TWO independent batch groups
// (warps 0-7 = group 0, warps 8-15 = group 1) sharing one 64KB Wr slab.
// Each group runs the proven R12 exchange machine (own fr/pk/sb/red/mbars,
// named barriers). Pairing is now guaranteed on every SM: while group g waits
// on its exchange, group g^1's IMMA burst fills the tensor pipe.
__global__ void __launch_bounds__(512, 1)
k_scan(const float* __restrict__ b2, const float* __restrict__ br2)
{
    extern __shared__ char sm[];
    // [0, 65536)              Wr slab (shared by both groups)
    // per group g at G = 65536 + g*13312:
    //   [G, G+8448)           frag[32][33] u64
    //   [G+8448, G+10752)     pk[2][8][36]
    //   [G+10752, G+11264)    sb[8][64]
    //   [G+11264, G+13312)    red[8][64]
    // [92160, 92192)          mbar[2 groups][2]
    const int GS = 13312, MB_OFF = 92160;

    int t   = threadIdx.x;
    int grp = t >> 8;
    int tl  = t & 255;
    int G   = 65536 + grp * GS;
    unsigned long long* fr  = (unsigned long long*)(sm + G);
    unsigned*           pk  = (unsigned*)(sm + G + 8448);
    unsigned char*      sb  = (unsigned char*)(sm + G + 10752);
    int*                red = (int*)(sm + G + 11264);

    int cr = blockIdx.x & 15;                 // rank in 16-CTA cluster
    int b0 = (blockIdx.x >> 4) * 16 + grp * 8; // batch base of this group
    int h0 = cr * 64;                          // h base (64 rows/CTA)

    uint32_t smb  = smem_u32(sm);
    uint32_t pk_a = smb + (uint32_t)(G + 8448);
    uint32_t mb_a = smb + (uint32_t)(MB_OFF + grp * 16);

    // ---- init: shared Wr slab (all 512 thr), per-group pk zero, mbars ----
    const int4* Wr4 = (const int4*)g_Wrq;
    int4* wS4 = (int4*)sm;
    for (int idx = t; idx < 4096; idx += 512) {
        int hh = idx >> 6, u = idx & 63;
        wS4[hh * 64 + (u ^ (hh & 7))] = Wr4[(h0 + hh) * 64 + u];
    }
    for (int i = tl; i < 576; i += 256) pk[i] = 0u;
    if (tl == 0) {
        asm volatile("mbarrier.init.shared.b64 [%0], 1;" :: "r"(mb_a) : "memory");
        asm volatile("mbarrier.init.shared.b64 [%0], 1;" :: "r"(mb_a + 8) : "memory");
    }
    __syncthreads();

    int lane = t & 31, w = t >> 5;
    int wl = w & 7;                       // warp within group
    int wg = wl & 3, kh = wl >> 2;        // m-tile 0-3, K-half 0/1
    int qd = lane >> 2;
    int qm = lane & 3;
    int h_lo = 16 * wg + qd;              // local h: h_lo, h_lo+8
    int bl0  = qm * 2;

    int mm  = lane >> 3, r8 = lane & 7;
    int lrow = 16 * wg + ((mm & 1) << 3) + r8;   // local row 0..63
    int uhi  = mm >> 1;
    uint32_t arow = smb + (uint32_t)lrow * 1024u;
    int kc0 = kh * 16;

    unsigned aR[16][4];
#pragma unroll
    for (int kc = 0; kc < 16; kc++) {
        uint32_t addr = arow + (uint32_t)((((kc0 + kc) * 2 + uhi) ^ r8) << 4);
        asm volatile(
            "ldmatrix.sync.aligned.m8n8.x4.shared.b16 {%0,%1,%2,%3}, [%4];"
            : "=r"(aR[kc][0]), "=r"(aR[kc][1]), "=r"(aR[kc][2]), "=r"(aR[kc][3])
            : "r"(addr));
    }

    asm volatile("barrier.cluster.arrive.aligned;" ::: "memory");
    asm volatile("barrier.cluster.wait.aligned;" ::: "memory");

    float b2lo = 0.f, b2hi = 0.f, brlo = 0.f, brhi = 0.f;
    if (kh == 0) {
        b2lo = b2[h0 + h_lo]; b2hi = b2[h0 + h_lo + 8];
        brlo = br2[h0 + h_lo]; brhi = br2[h0 + h_lo + 8];
    }

    float mem[4] = {0.f, 0.f, 0.f, 0.f};
    float spf[4] = {0.f, 0.f, 0.f, 0.f};
    int   cnt[4] = {0, 0, 0, 0};
    unsigned ph[2] = {0u, 0u};

    const float* Ib = g_I + (size_t)b0 * 1024 + h0;
    float Iv0 = 0.f, Iv1 = 0.f, Iv2 = 0.f, Iv3 = 0.f;
    if (kh == 0) {
        Iv0 = Ib[(size_t)(bl0    ) * 1024 + h_lo];
        Iv1 = Ib[(size_t)(bl0 + 1) * 1024 + h_lo];
        Iv2 = Ib[(size_t)(bl0    ) * 1024 + h_lo + 8];
        Iv3 = Ib[(size_t)(bl0 + 1) * 1024 + h_lo + 8];
    }

    int tt = tl & 127;                    // kh1 staging id within group
    int barF = 2 + grp;                   // full-group barrier (256)
    int barH = 4 + grp;                   // kh0-only barrier (128)

    for (int s = 0; s < 1024; s++) {
        int q = s & 1, qn = q ^ 1;

        if (tl == 0) {
            asm volatile(
                "mbarrier.arrive.expect_tx.shared::cta.b64 _, [%0], %1;"
                :: "r"(mb_a + (uint32_t)qn * 8u), "r"(1024u) : "memory");
        }

        if (kh == 1) {
            if (s > 0) {
                unsigned par = ph[q];
                ph[q] ^= 1u;
                unsigned done;
                do {
                    asm volatile(
                        "{\n\t.reg .pred p;\n\t"
                        "mbarrier.try_wait.parity.acquire.cluster.shared::cta.b64 p, [%1], %2;\n\t"
                        "selp.b32 %0, 1, 0, p;\n\t}"
                        : "=r"(done) : "r"(mb_a + (uint32_t)q * 8u), "r"(par) : "memory");
                } while (!done);
            }
#pragma unroll
            for (int j = 0; j < 2; j++) {
                int idx = tt + j * 128;
                int eqd = idx >> 5, ekc = idx & 31;
                unsigned wbits = pk[q * 288 + eqd * 36 + ekc];
                unsigned long long* frow = fr + ekc * 33 + eqd * 4;
#pragma unroll
                for (int jj = 0; jj < 4; jj++) {
                    unsigned u0 = (wbits >> (jj * 4)) & 0xFu;
                    unsigned u1 = (wbits >> (jj * 4 + 16)) & 0xFu;
                    unsigned lo = (u0 * 0x204081u) & 0x01010101u;
                    unsigned hi = (u1 * 0x204081u) & 0x01010101u;
                    frow[jj] = ((unsigned long long)hi << 32) | (unsigned long long)lo;
                }
            }
        }
        asm volatile("bar.sync %0, 256;" :: "r"(barF) : "memory");  // sync1

        int c[16];
#pragma unroll
        for (int i = 0; i < 16; i++) c[i] = 0;

        const unsigned long long* fl = fr + kc0 * 33 + lane;
#pragma unroll
        for (int kc = 0; kc < 16; kc++) {
            unsigned long long bb = fl[kc * 33];
            unsigned bb0 = (unsigned)bb;
            unsigned bb1 = (unsigned)(bb >> 32);
            int* cc = c + (kc & 3) * 4;
            asm volatile(
                "mma.sync.aligned.m16n8k32.row.col.s32.s8.s8.s32 "
                "{%0,%1,%2,%3}, {%4,%5,%6,%7}, {%8,%9}, {%0,%1,%2,%3};"
                : "+r"(cc[0]), "+r"(cc[1]), "+r"(cc[2]), "+r"(cc[3])
                : "r"(aR[kc][0]), "r"(aR[kc][1]), "r"(aR[kc][2]), "r"(aR[kc][3]),
                  "r"(bb0), "r"(bb1));
        }
        int accs[4];
#pragma unroll
        for (int i = 0; i < 4; i++)
            accs[i] = (c[i] + c[4 + i]) + (c[8 + i] + c[12 + i]);

        if (kh == 1) {
#pragma unroll
            for (int r = 0; r < 4; r++) {
                int hh = h_lo + ((r >= 2) ? 8 : 0);
                int bb = bl0 + (r & 1);
                red[bb * 64 + hh] = accs[r];
            }
        }
        asm volatile("bar.sync %0, 256;" :: "r"(barF) : "memory");  // sync2

        if (kh == 0) {
            float Ivs[4] = {Iv0, Iv1, Iv2, Iv3};
#pragma unroll
            for (int r = 0; r < 4; r++) {
                int hh = h_lo + ((r >= 2) ? 8 : 0);
                int bb = bl0 + (r & 1);
                int a = accs[r] + red[bb * 64 + hh];
                float R = (float)a * 0.0625f;                 // exact
                float m = __fmul_rn(mem[r], 0.2f);
                if (spf[r] != 0.f) m = 0.f;                   // *(1-spike)
                m = __fadd_rn(m, Ivs[r]);
                m = __fadd_rn(m, (r >= 2) ? b2hi : b2lo);
                m = __fadd_rn(m, R);
                m = __fadd_rn(m, (r >= 2) ? brhi : brlo);
                mem[r] = m;
                bool sk = m > 0.5f;
                spf[r] = sk ? 1.f : 0.f;
                cnt[r] += sk ? 1 : 0;
                sb[bb * 64 + hh] = sk ? 1u : 0u;
            }
            asm volatile("bar.sync %0, 128;" :: "r"(barH) : "memory");

            unsigned w00 = __ballot_sync(0xffffffffu, sb[(2 * wg    ) * 64      + lane] != 0);
            unsigned w01 = __ballot_sync(0xffffffffu, sb[(2 * wg    ) * 64 + 32 + lane] != 0);
            unsigned w10 = __ballot_sync(0xffffffffu, sb[(2 * wg + 1) * 64      + lane] != 0);
            unsigned w11 = __ballot_sync(0xffffffffu, sb[(2 * wg + 1) * 64 + 32 + lane] != 0);

            int rank = lane >> 1;
            int wi   = lane & 1;
            uint32_t mbr = mb_a + (uint32_t)qn * 8u;
#pragma unroll
            for (int r = 0; r < 2; r++) {
                int batch = 2 * wg + r;
                unsigned word = r ? (wi ? w11 : w10) : (wi ? w01 : w00);
                uint32_t dst = pk_a + (uint32_t)(qn * 288 + batch * 36 + cr * 2 + wi) * 4u;
                asm volatile(
                    "{\n\t.reg .b32 ra, rb;\n\t"
                    "mapa.shared::cluster.u32 ra, %0, %1;\n\t"
                    "mapa.shared::cluster.u32 rb, %2, %1;\n\t"
                    "st.async.shared::cluster.mbarrier::complete_tx::bytes.b32 [ra], %3, [rb];\n\t}"
                    :: "r"(dst), "r"(rank), "r"(mbr), "r"(word) : "memory");
            }

            if (s < 1023) Ib += 131072;
            Iv0 = Ib[(size_t)(bl0    ) * 1024 + h_lo];
            Iv1 = Ib[(size_t)(bl0 + 1) * 1024 + h_lo];
            Iv2 = Ib[(size_t)(bl0    ) * 1024 + h_lo + 8];
            Iv3 = Ib[(size_t)(bl0 + 1) * 1024 + h_lo + 8];
        }
    }

    if (kh == 0) {
#pragma unroll
        for (int r = 0; r < 4; r++) {
            int hh = h_lo + ((r >= 2) ? 8 : 0);
            int bb = bl0 + (r & 1);
            g_sum[(b0 + bb) * 1024 + h0 + hh] = (float)cnt[r];
        }
    }

    // no CTA may exit while peers' st.async targeting it can be in flight
    asm volatile("barrier.cluster.arrive.aligned;" ::: "memory");
    asm volatile("barrier.cluster.wait.aligned;" ::: "memory");
}

// ---------------- K4: readout ---------------------------------------------
__global__ void k_out(const float* __restrict__ W3, const float* __restrict__ b3,
                      float* __restrict__ out)
{
    __shared__ float s0[128], s1[128];
    int b = blockIdx.x, t = threadIdx.x;
    float a0 = 0.f, a1 = 0.f;
    for (int hh = t; hh < 1024; hh += 128) {
        float s = g_sum[b * 1024 + hh];
        a0 += s * W3[hh];
        a1 += s * W3[1024 + hh];
    }
    s0[t] = a0; s1[t] = a1;
    __syncthreads();
    for (int o = 64; o > 0; o >>= 1) {
        if (t < o) { s0[t] += s0[t + o]; s1[t] += s1[t + o]; }
        __syncthreads();
    }
    if (t == 0) {
        out[b * 2 + 0] = s0[0] + b3[0];
        out[b * 2 + 1] = s1[0] + b3[1];
    }
}

// ---------------- launch ----------------------------------------------------
extern "C" void kernel_launch(void* const* d_in, const int* in_sizes, int n_in,
                              void* d_out, int out_size)
{
    const int*   inputs = (const int*)d_in[0];
    const float* emb    = (const float*)d_in[1];
    const float* W1     = (const float*)d_in[2];
    const float* b1     = (const float*)d_in[3];
    const float* W2     = (const float*)d_in[4];
    const float* b2     = (const float*)d_in[5];
    const float* Wr2    = (const float*)d_in[6];
    const float* br2    = (const float*)d_in[7];
    const float* W3     = (const float*)d_in[8];
    const float* b3     = (const float*)d_in[9];
    float* out = (float*)d_out;

    cudaFuncSetAttribute(k_embed_l1, cudaFuncAttributeMaxDynamicSharedMemorySize, 131072);
    cudaFuncSetAttribute(k_gemm_I,  cudaFuncAttributeMaxDynamicSharedMemorySize, 71808);
    cudaFuncSetAttribute(k_scan,    cudaFuncAttributeMaxDynamicSharedMemorySize, 92192);
    cudaFuncSetAttribute(k_scan,    cudaFuncAttributeNonPortableClusterSizeAllowed, 1);

    k_quant<<<(H_ * H_ + 255) / 256, 256>>>(W2, Wr2);
    k_embed_l1<<<2048, 256, 130816>>>(inputs, emb, W1, b1);
    k_gemm_I<<<dim3(8, 1024), 256, 71808>>>();

    {
        cudaLaunchConfig_t cfg = {};
        cfg.gridDim = dim3(128, 1, 1);
        cfg.blockDim = dim3(512, 1, 1);
        cfg.dynamicSmemBytes = 92192;
        cfg.stream = 0;
        cudaLaunchAttribute at[1];
        at[0].id = cudaLaunchAttributeClusterDimension;
        at[0].val.clusterDim.x = 16;
        at[0].val.clusterDim.y = 1;
        at[0].val.clusterDim.z = 1;
        cfg.attrs = at;
        cfg.numAttrs = 1;
        cudaLaunchKernelEx(&cfg, k_scan, b2, br2);
    }

    k_out<<<128, 128>>>(W3, b3, out);
}

// round 17
// speedup vs baseline: 1.1850x; 1.1850x over previous
#include <cuda_runtime.h>
#include <cstdint>

#define B_    128
#define S_    1024
#define EMB_  100
#define EDIM_ 256
#define H_    1024

// Scratch (device globals: allocation-free rule)
__device__ float       g_I[S_ * B_ * H_];      // [s*128+b][h]  512 MB
__device__ signed char g_Xq[S_ * B_ * EDIM_];  // quantized layer-1 acts *16
__device__ signed char g_W2q[H_ * EDIM_];      // round(W2*16)
__device__ signed char g_Wrq[H_ * H_];         // round(Wr2*16)
__device__ float       g_sum[B_ * H_];         // spike counts

__device__ __forceinline__ uint32_t smem_u32(const void* p) {
    uint32_t a;
    asm("{ .reg .u64 t; cvta.to.shared.u64 t, %1; cvt.u32.u64 %0, t; }" : "=r"(a) : "l"(p));
    return a;
}

// ---------------- K0: weight quantization --------------------------------
__global__ void k_quant(const float* __restrict__ W2, const float* __restrict__ Wr2) {
    int i = blockIdx.x * blockDim.x + threadIdx.x;
    if (i < H_ * EDIM_) {
        float v = rintf(W2[i] * 16.f);
        v = fminf(fmaxf(v, -15.f), 15.f);
        g_W2q[i] = (signed char)v;
    }
    if (i < H_ * H_) {
        float v = rintf(Wr2[i] * 16.f);
        v = fminf(fmaxf(v, -15.f), 15.f);
        g_Wrq[i] = (signed char)v;
    }
}

// ---------------- K1: embedding + layer1 + quant_act ----------------------
__global__ __launch_bounds__(256) void k_embed_l1(
    const int* __restrict__ inputs, const float* __restrict__ emb,
    const float* __restrict__ W1, const float* __restrict__ b1)
{
    extern __shared__ char sm[];
    float* w1t = (float*)sm;               // [100][257]
    float* xs  = (float*)(sm + 102912);    // [64][104]
    float* b1s = (float*)(sm + 129536);
    int*   tok = (int*)(sm + 130560);

    int t = threadIdx.x;
    for (int idx = t; idx < EDIM_ * EMB_; idx += 256) {
        int h = idx / EMB_;
        int e = idx - h * EMB_;
        w1t[e * 257 + h] = W1[idx];
    }
    b1s[t] = b1[t];
    int r0 = blockIdx.x * 64;
    if (t < 64) {
        int R = r0 + t;
        tok[t] = inputs[(R & 127) * S_ + (R >> 7)];
    }
    __syncthreads();
    for (int idx = t; idx < 64 * 104; idx += 256) {
        int r = idx / 104;
        int e = idx - r * 104;
        xs[idx] = (e < EMB_) ? emb[tok[r] * EMB_ + e] : 0.f;
    }
    __syncthreads();

    int h = t;
    for (int rb = 0; rb < 8; rb++) {
        float acc[8];
#pragma unroll
        for (int i = 0; i < 8; i++) acc[i] = 0.f;
        for (int ec = 0; ec < 25; ec++) {
            float w0 = w1t[(4 * ec + 0) * 257 + h];
            float w1v = w1t[(4 * ec + 1) * 257 + h];
            float w2v = w1t[(4 * ec + 2) * 257 + h];
            float w3v = w1t[(4 * ec + 3) * 257 + h];
#pragma unroll
            for (int r8 = 0; r8 < 8; r8++) {
                const float4 x4 = *(const float4*)(xs + (rb * 8 + r8) * 104 + 4 * ec);
                acc[r8] += x4.x * w0 + x4.y * w1v + x4.z * w2v + x4.w * w3v;
            }
        }
#pragma unroll
        for (int r8 = 0; r8 < 8; r8++) {
            int R = r0 + rb * 8 + r8;
            float v = acc[r8] + b1s[h];
            v = fmaxf(v, 0.f);
            float q = fminf(rintf(v * 16.f), 15.f);
            g_Xq[R * EDIM_ + h] = (signed char)q;
        }
    }
}

// ---------------- K2: I = Xq @ W2q^T / 256 (IMMA, 4x2 chains) ---------------
// R14 structure; inner 8 IMMA now 4 independent chains x 2 deep to cut the
// dependency tail. Integer accumulation order-free -> g_I bit-identical.
__global__ __launch_bounds__(256, 2) void k_gemm_I() {
    extern __shared__ char sm[];
    // [0, 32768)        W2 tile: 128 rows x 256 B, 16B-unit XOR swizzle
    // [32768, 67584)    Xq tile: 128 rows x 272 B
    // [67584, 71808)    stage: 8 rows x 132 floats
    int t = threadIdx.x, lane = t & 31, w = t >> 5;
    int ht0 = blockIdx.x * 128;
    int rt0 = blockIdx.y * 128;
    uint32_t smb = smem_u32(sm);
    float* stage = (float*)(sm + 67584);

    const int4* W24 = (const int4*)g_W2q;
    int4* wS2 = (int4*)sm;
    for (int idx = t; idx < 2048; idx += 256) {
        int hh = idx >> 4, u = idx & 15;
        wS2[hh * 16 + (u ^ (hh & 7))] = W24[(ht0 + hh) * 16 + u];
    }
    {
        const unsigned long long* Xs =
            (const unsigned long long*)(g_Xq + (size_t)rt0 * 256);
#pragma unroll
        for (int j = 0; j < 16; j++) {
            int idx = t + j * 256;
            int row = idx >> 5, u = idx & 31;
            *(unsigned long long*)(sm + 32768 + row * 272 + u * 8) = Xs[row * 32 + u];
        }
    }
    __syncthreads();

    int mm = lane >> 3, r8 = lane & 7;
    int lrow = 16 * w + ((mm & 1) << 3) + r8;
    int uhi = mm >> 1;
    uint32_t arow = smb + (uint32_t)lrow * 256u;
    unsigned aR[8][4];
#pragma unroll
    for (int kc = 0; kc < 8; kc++) {
        uint32_t aaddr = arow + (uint32_t)(((kc * 2 + uhi) ^ r8) << 4);
        asm volatile(
            "ldmatrix.sync.aligned.m8n8.x4.shared.b16 {%0,%1,%2,%3}, [%4];"
            : "=r"(aR[kc][0]), "=r"(aR[kc][1]), "=r"(aR[kc][2]), "=r"(aR[kc][3])
            : "r"(aaddr));
    }

    int qd = lane >> 2, qm = lane & 3;
    int cw = 16 * w + qd;               // local output column
    uint32_t xb0 = smb + 32768u + (uint32_t)(qd * 272 + qm * 4);

    for (int n = 0; n < 16; n++) {
        uint32_t xb = xb0 + (uint32_t)(n * 8 * 272);
        int c[16];
#pragma unroll
        for (int i = 0; i < 16; i++) c[i] = 0;
#pragma unroll
        for (int kc = 0; kc < 8; kc++) {
            unsigned b0v, b1v;
            asm volatile("ld.shared.b32 %0, [%1];" : "=r"(b0v) : "r"(xb + kc * 32));
            asm volatile("ld.shared.b32 %0, [%1];" : "=r"(b1v) : "r"(xb + kc * 32 + 16));
            int* cc = c + (kc & 3) * 4;   // 4 chains x 2 deep
            asm volatile(
                "mma.sync.aligned.m16n8k32.row.col.s32.s8.s8.s32 "
                "{%0,%1,%2,%3}, {%4,%5,%6,%7}, {%8,%9}, {%0,%1,%2,%3};"
                : "+r"(cc[0]), "+r"(cc[1]), "+r"(cc[2]), "+r"(cc[3])
                : "r"(aR[kc][0]), "r"(aR[kc][1]), "r"(aR[kc][2]), "r"(aR[kc][3]),
                  "r"(b0v), "r"(b1v));
        }
        float v0 = (float)((c[0] + c[4]) + (c[8]  + c[12])) * (1.f / 256.f);
        float v1 = (float)((c[1] + c[5]) + (c[9]  + c[13])) * (1.f / 256.f);
        float v2 = (float)((c[2] + c[6]) + (c[10] + c[14])) * (1.f / 256.f);
        float v3 = (float)((c[3] + c[7]) + (c[11] + c[15])) * (1.f / 256.f);
        stage[(qm * 2    ) * 132 + cw    ] = v0;
        stage[(qm * 2 + 1) * 132 + cw    ] = v1;
        stage[(qm * 2    ) * 132 + cw + 8] = v2;
        stage[(qm * 2 + 1) * 132 + cw + 8] = v3;
        __syncthreads();
        {
            float4 v = *(float4*)(stage + w * 132 + lane * 4);
            *(float4*)(&g_I[(size_t)(rt0 + n * 8 + w) * 1024 + ht0 + lane * 4]) = v;
        }
        __syncthreads();
    }
}

// ---------------- K3: recurrent LIF scan (v16) ------------------------------
// R12 protocol (16x16 cluster, 2 CTAs/SM, st.async + expect_tx mbarriers,
// K-split warps kh0/kh1, resident A-frags, 4x4 chains) with the staging
// phase REMOVED: all warps wait on the mbar directly, and each lane builds
// its B-fragment inline from pk bits (1 broadcast LDS.32 + 6 ALU per chunk).
// Deletes per-step: fr staging stores + one full 256-thread barrier.
__global__ void __launch_bounds__(256, 2)
k_scan(const float* __restrict__ b2, const float* __restrict__ br2)
{
    extern __shared__ char sm[];
    // [0, 65536)         Wr slab: 64 rows x 1024 B, 16B-unit XOR swizzle
    // [65536, 67840)     pk[2][8][36] packed spike words
    // [67840, 68352)     sb[8][64] spike byte staging
    // [68352, 70400)     red[8][64] int partial sums
    // [70400, 70416)     mbar[2]
    const int PK_OFF = 65536, SB_OFF = 67840, RED_OFF = 68352, MB_OFF = 70400;
    unsigned*      pk  = (unsigned*)(sm + PK_OFF);
    unsigned char* sb  = (unsigned char*)(sm + SB_OFF);
    int*           red = (int*)(sm + RED_OFF);

    int t  = threadIdx.x;
    int cr = blockIdx.x & 15;           // rank in 16-CTA cluster
    int b0 = (blockIdx.x >> 4) * 8;     // global batch base
    int h0 = cr * 64;                   // global h base (64 rows/CTA)

    uint32_t smb  = smem_u32(sm);
    uint32_t pk_a = smb + PK_OFF;
    uint32_t mb_a = smb + MB_OFF;

    const int4* Wr4 = (const int4*)g_Wrq;
    int4* wS4 = (int4*)sm;
    for (int idx = t; idx < 4096; idx += 256) {
        int hh = idx >> 6, u = idx & 63;
        wS4[hh * 64 + (u ^ (hh & 7))] = Wr4[(h0 + hh) * 64 + u];
    }
    for (int i = t; i < 576; i += 256) pk[i] = 0u;
    if (t == 0) {
        asm volatile("mbarrier.init.shared.b64 [%0], 1;" :: "r"(mb_a) : "memory");
        asm volatile("mbarrier.init.shared.b64 [%0], 1;" :: "r"(mb_a + 8) : "memory");
    }
    __syncthreads();

    int lane = t & 31, w = t >> 5;
    int wg = w & 3, kh = w >> 2;        // m-tile 0-3, K-half 0/1
    int qd = lane >> 2;
    int qm = lane & 3;
    int h_lo = 16 * wg + qd;            // local h: h_lo, h_lo+8
    int bl0  = qm * 2;
    int sb4  = qm * 4;                  // nibble base within pk word

    int mm  = lane >> 3, r8 = lane & 7;
    int lrow = 16 * wg + ((mm & 1) << 3) + r8;   // local row 0..63
    int uhi  = mm >> 1;
    uint32_t arow = smb + (uint32_t)lrow * 1024u;
    int kc0 = kh * 16;

    unsigned aR[16][4];
#pragma unroll
    for (int kc = 0; kc < 16; kc++) {
        uint32_t addr = arow + (uint32_t)((((kc0 + kc) * 2 + uhi) ^ r8) << 4);
        asm volatile(
            "ldmatrix.sync.aligned.m8n8.x4.shared.b16 {%0,%1,%2,%3}, [%4];"
            : "=r"(aR[kc][0]), "=r"(aR[kc][1]), "=r"(aR[kc][2]), "=r"(aR[kc][3])
            : "r"(addr));
    }

    asm volatile("barrier.cluster.arrive.aligned;" ::: "memory");
    asm volatile("barrier.cluster.wait.aligned;" ::: "memory");

    float b2lo = 0.f, b2hi = 0.f, brlo = 0.f, brhi = 0.f;
    if (kh == 0) {
        b2lo = b2[h0 + h_lo]; b2hi = b2[h0 + h_lo + 8];
        brlo = br2[h0 + h_lo]; brhi = br2[h0 + h_lo + 8];
    }

    float mem[4] = {0.f, 0.f, 0.f, 0.f};
    float spf[4] = {0.f, 0.f, 0.f, 0.f};
    int   cnt[4] = {0, 0, 0, 0};
    unsigned ph[2] = {0u, 0u};

    const float* Ib = g_I + (size_t)b0 * 1024 + h0;
    float Iv0 = 0.f, Iv1 = 0.f, Iv2 = 0.f, Iv3 = 0.f;
    if (kh == 0) {
        Iv0 = Ib[(size_t)(bl0    ) * 1024 + h_lo];
        Iv1 = Ib[(size_t)(bl0 + 1) * 1024 + h_lo];
        Iv2 = Ib[(size_t)(bl0    ) * 1024 + h_lo + 8];
        Iv3 = Ib[(size_t)(bl0 + 1) * 1024 + h_lo + 8];
    }

    for (int s = 0; s < 1024; s++) {
        int q = s & 1, qn = q ^ 1;

        if (t == 0) {
            asm volatile(
                "mbarrier.arrive.expect_tx.shared::cta.b64 _, [%0], %1;"
                :: "r"(mb_a + (uint32_t)qn * 8u), "r"(1024u) : "memory");
        }

        // all warps wait for this step's spike words (step 0 pre-zeroed)
        if (s > 0) {
            unsigned par = ph[q];
            ph[q] ^= 1u;
            unsigned done;
            do {
                asm volatile(
                    "{\n\t.reg .pred p;\n\t"
                    "mbarrier.try_wait.parity.acquire.cluster.shared::cta.b64 p, [%1], %2;\n\t"
                    "selp.b32 %0, 1, 0, p;\n\t}"
                    : "=r"(done) : "r"(mb_a + (uint32_t)q * 8u), "r"(par) : "memory");
            } while (!done);
        }

        // ---- MMA: inline B-frag from pk bits, 4 chains x 4 deep ----
        int c[16];
#pragma unroll
        for (int i = 0; i < 16; i++) c[i] = 0;

        const unsigned* pkq = pk + q * 288 + qd * 36 + kc0;
#pragma unroll
        for (int kc = 0; kc < 16; kc++) {
            unsigned wbits = pkq[kc];                 // broadcast LDS.32
            unsigned u0 = (wbits >> sb4) & 0xFu;
            unsigned u1 = (wbits >> (sb4 + 16)) & 0xFu;
            unsigned bb0 = (u0 * 0x204081u) & 0x01010101u;
            unsigned bb1 = (u1 * 0x204081u) & 0x01010101u;
            int* cc = c + (kc & 3) * 4;
            asm volatile(
                "mma.sync.aligned.m16n8k32.row.col.s32.s8.s8.s32 "
                "{%0,%1,%2,%3}, {%4,%5,%6,%7}, {%8,%9}, {%0,%1,%2,%3};"
                : "+r"(cc[0]), "+r"(cc[1]), "+r"(cc[2]), "+r"(cc[3])
                : "r"(aR[kc][0]), "r"(aR[kc][1]), "r"(aR[kc][2]), "r"(aR[kc][3]),
                  "r"(bb0), "r"(bb1));
        }
        int accs[4];
#pragma unroll
        for (int i = 0; i < 4; i++)
            accs[i] = (c[i] + c[4 + i]) + (c[8 + i] + c[12 + i]);

        if (kh == 1) {
#pragma unroll
            for (int r = 0; r < 4; r++) {
                int hh = h_lo + ((r >= 2) ? 8 : 0);
                int bb = bl0 + (r & 1);
                red[bb * 64 + hh] = accs[r];
            }
        }
        __syncthreads();   // sync2: partials visible; pk[q] reads complete

        if (kh == 0) {
            float Ivs[4] = {Iv0, Iv1, Iv2, Iv3};
#pragma unroll
            for (int r = 0; r < 4; r++) {
                int hh = h_lo + ((r >= 2) ? 8 : 0);
                int bb = bl0 + (r & 1);
                int a = accs[r] + red[bb * 64 + hh];
                float R = (float)a * 0.0625f;                 // exact
                float m = __fmul_rn(mem[r], 0.2f);
                if (spf[r] != 0.f) m = 0.f;                   // *(1-spike)
                m = __fadd_rn(m, Ivs[r]);
                m = __fadd_rn(m, (r >= 2) ? b2hi : b2lo);
                m = __fadd_rn(m, R);
                m = __fadd_rn(m, (r >= 2) ? brhi : brlo);
                mem[r] = m;
                bool sk = m > 0.5f;
                spf[r] = sk ? 1.f : 0.f;
                cnt[r] += sk ? 1 : 0;
                sb[bb * 64 + hh] = sk ? 1u : 0u;
            }
            asm volatile("bar.sync 1, 128;" ::: "memory");   // kh0 warps only

            unsigned w00 = __ballot_sync(0xffffffffu, sb[(2 * wg    ) * 64      + lane] != 0);
            unsigned w01 = __ballot_sync(0xffffffffu, sb[(2 * wg    ) * 64 + 32 + lane] != 0);
            unsigned w10 = __ballot_sync(0xffffffffu, sb[(2 * wg + 1) * 64      + lane] != 0);
            unsigned w11 = __ballot_sync(0xffffffffu, sb[(2 * wg + 1) * 64 + 32 + lane] != 0);

            int rank = lane >> 1;
            int wi   = lane & 1;
            uint32_t mbr = mb_a + (uint32_t)qn * 8u;
#pragma unroll
            for (int r = 0; r < 2; r++) {
                int batch = 2 * wg + r;
                unsigned word = r ? (wi ? w11 : w10) : (wi ? w01 : w00);
                uint32_t dst = pk_a + (uint32_t)(qn * 288 + batch * 36 + cr * 2 + wi) * 4u;
                asm volatile(
                    "{\n\t.reg .b32 ra, rb;\n\t"
                    "mapa.shared::cluster.u32 ra, %0, %1;\n\t"
                    "mapa.shared::cluster.u32 rb, %2, %1;\n\t"
                    "st.async.shared::cluster.mbarrier::complete_tx::bytes.b32 [ra], %3, [rb];\n\t}"
                    :: "r"(dst), "r"(rank), "r"(mbr), "r"(word) : "memory");
            }

            if (s < 1023) Ib += 131072;
            Iv0 = Ib[(size_t)(bl0    ) * 1024 + h_lo];
            Iv1 = Ib[(size_t)(bl0 + 1) * 1024 + h_lo];
            Iv2 = Ib[(size_t)(bl0    ) * 1024 + h_lo + 8];
            Iv3 = Ib[(size_t)(bl0 + 1) * 1024 + h_lo + 8];
        }
    }

    if (kh == 0) {
#pragma unroll
        for (int r = 0; r < 4; r++) {
            int hh = h_lo + ((r >= 2) ? 8 : 0);
            int bb = bl0 + (r & 1);
            g_sum[(b0 + bb) * 1024 + h0 + hh] = (float)cnt[r];
        }
    }

    // no CTA may exit while peers' st.async targeting it can be in flight
    asm volatile("barrier.cluster.arrive.aligned;" ::: "memory");
    asm volatile("barrier.cluster.wait.aligned;" ::: "memory");
}

// ---------------- K4: readout ---------------------------------------------
__global__ void k_out(const float* __restrict__ W3, const float* __restrict__ b3,
                      float* __restrict__ out)
{
    __shared__ float s0[128], s1[128];
    int b = blockIdx.x, t = threadIdx.x;
    float a0 = 0.f, a1 = 0.f;
    for (int hh = t; hh < 1024; hh += 128) {
        float s = g_sum[b * 1024 + hh];
        a0 += s * W3[hh];
        a1 += s * W3[1024 + hh];
    }
    s0[t] = a0; s1[t] = a1;
    __syncthreads();
    for (int o = 64; o > 0; o >>= 1) {
        if (t < o) { s0[t] += s0[t + o]; s1[t] += s1[t + o]; }
        __syncthreads();
    }
    if (t == 0) {
        out[b * 2 + 0] = s0[0] + b3[0];
        out[b * 2 + 1] = s1[0] + b3[1];
    }
}

// ---------------- launch ----------------------------------------------------
extern "C" void kernel_launch(void* const* d_in, const int* in_sizes, int n_in,
                              void* d_out, int out_size)
{
    const int*   inputs = (const int*)d_in[0];
    const float* emb    = (const float*)d_in[1];
    const float* W1     = (const float*)d_in[2];
    const float* b1     = (const float*)d_in[3];
    const float* W2     = (const float*)d_in[4];
    const float* b2     = (const float*)d_in[5];
    const float* Wr2    = (const float*)d_in[6];
    const float* br2    = (const float*)d_in[7];
    const float* W3     = (const float*)d_in[8];
    const float* b3     = (const float*)d_in[9];
    float* out = (float*)d_out;

    cudaFuncSetAttribute(k_embed_l1, cudaFuncAttributeMaxDynamicSharedMemorySize, 131072);
    cudaFuncSetAttribute(k_gemm_I,  cudaFuncAttributeMaxDynamicSharedMemorySize, 71808);
    cudaFuncSetAttribute(k_scan,    cudaFuncAttributeMaxDynamicSharedMemorySize, 70416);
    cudaFuncSetAttribute(k_scan,    cudaFuncAttributeNonPortableClusterSizeAllowed, 1);

    k_quant<<<(H_ * H_ + 255) / 256, 256>>>(W2, Wr2);
    k_embed_l1<<<2048, 256, 130816>>>(inputs, emb, W1, b1);
    k_gemm_I<<<dim3(8, 1024), 256, 71808>>>();

    {
        cudaLaunchConfig_t cfg = {};
        cfg.gridDim = dim3(256, 1, 1);
        cfg.blockDim = dim3(256, 1, 1);
        cfg.dynamicSmemBytes = 70416;
        cfg.stream = 0;
        cudaLaunchAttribute at[1];
        at[0].id = cudaLaunchAttributeClusterDimension;
        at[0].val.clusterDim.x = 16;
        at[0].val.clusterDim.y = 1;
        at[0].val.clusterDim.z = 1;
        cfg.attrs = at;
        cfg.numAttrs = 1;
        cudaLaunchKernelEx(&cfg, k_scan, b2, br2);
    }

    k_out<<<128, 128>>>(W3, b3, out);
}